// round 15
// baseline (speedup 1.0000x reference)
#include <cuda_runtime.h>
#include <math.h>
#include <stdint.h>

#define BATCH 64
#define SEQT  2048
#define ISZ   256
#define HSZ   1024

// ---------------------------------------------------------------------------
// Global scratch (module-compact layouts).
//  XP_m[k][b][128] : input projection at module-m active times (t = k<<m)
//  HT_m[k][b][128] : module-m hidden trajectory samples
//  U_j [k][b][128j]: Whh[0:128j, j-block] @ h_j^(k)
//  C_m [k][b][256] : fc_w[:, m-block] @ h_m^(k)
// ---------------------------------------------------------------------------
#define XP_TOT 33423360ull
#define U_TOT  32374784ull
#define C_TOT  66846720ull
static __device__ float g_xp[XP_TOT];
static __device__ float g_ht[XP_TOT];
static __device__ float g_u [U_TOT];
static __device__ float g_c [C_TOT];

__host__ __device__ constexpr size_t xpoff(int m) {
    return 8192ull * (size_t)(4096 - (4096 >> m));
}
__host__ __device__ constexpr size_t uoff(int j) {
    size_t s = 0;
    for (int p = 1; p < j; p++) s += (size_t)(2048 >> p) * 8192ull * (size_t)p;
    return s;
}
__host__ __device__ constexpr size_t coff(int m) {
    return 16384ull * (size_t)(4096 - (4096 >> m));
}

// ---------------------------------------------------------------------------
// TF32 3-split GEMM core (fp32-accurate): 128x128 CTA tile, 256 thr, 8 warps,
// warp tile 32x64, mma.m16n8k8, double-buffered smem stage.
// ---------------------------------------------------------------------------
__device__ __forceinline__ uint32_t f32_to_tf32(float x) {
    uint32_t r;
    asm("cvt.rna.tf32.f32 %0, %1;" : "=r"(r) : "f"(x));
    return r;
}
__device__ __forceinline__ void mma_tf32(float4& d, const uint32_t a[4],
                                         const uint32_t b0, const uint32_t b1) {
    asm volatile(
        "mma.sync.aligned.m16n8k8.row.col.f32.tf32.tf32.f32 "
        "{%0,%1,%2,%3}, {%4,%5,%6,%7}, {%8,%9}, {%0,%1,%2,%3};"
        : "+f"(d.x), "+f"(d.y), "+f"(d.z), "+f"(d.w)
        : "r"(a[0]), "r"(a[1]), "r"(a[2]), "r"(a[3]), "r"(b0), "r"(b1));
}

#define GST 4224
#define GEMM_SMEM_BYTES (2 * GST * 4)

__device__ __forceinline__ void stage_chunk(float* s, const float4 av, const float4 bv,
                                            int ldr, int ldk)
{
    const float a4[4] = {av.x, av.y, av.z, av.w};
    const float b4[4] = {bv.x, bv.y, bv.z, bv.w};
#pragma unroll
    for (int e = 0; e < 4; e++) {
        uint32_t hi = f32_to_tf32(a4[e]);
        float lo = a4[e] - __uint_as_float(hi);
        s[(ldk + e) * 132 + ldr]        = __uint_as_float(hi);
        s[1056 + (ldk + e) * 132 + ldr] = __uint_as_float(f32_to_tf32(lo));
        uint32_t bhi = f32_to_tf32(b4[e]);
        float blo = b4[e] - __uint_as_float(bhi);
        s[2112 + (ldk + e) * 132 + ldr] = __uint_as_float(bhi);
        s[3168 + (ldk + e) * 132 + ldr] = __uint_as_float(f32_to_tf32(blo));
    }
}

__device__ __forceinline__ void gemm_core(const float* Ag, const float* Bg,
                                          int kchunks, float* gsm,
                                          int ldr, int ldk, int m0, int n0, int tig,
                                          float4 acc[2][8])
{
    stage_chunk(gsm, *(const float4*)Ag, *(const float4*)Bg, ldr, ldk);
    __syncthreads();

    for (int kc = 0; kc < kchunks; kc++) {
        float4 av, bv;
        if (kc + 1 < kchunks) {
            av = *(const float4*)(Ag + (kc + 1) * 8);
            bv = *(const float4*)(Bg + (kc + 1) * 8);
        }
        const float* As_h = gsm + (kc & 1) * GST;
        const float* As_l = As_h + 1056;
        const float* Bs_h = As_h + 2112;
        const float* Bs_l = As_h + 3168;

        uint32_t ah[2][4], al[2][4];
#pragma unroll
        for (int mt = 0; mt < 2; mt++) {
            const int r = m0 + mt * 16;
            ah[mt][0] = __float_as_uint(As_h[tig * 132 + r]);
            ah[mt][1] = __float_as_uint(As_h[tig * 132 + r + 8]);
            ah[mt][2] = __float_as_uint(As_h[(tig + 4) * 132 + r]);
            ah[mt][3] = __float_as_uint(As_h[(tig + 4) * 132 + r + 8]);
            al[mt][0] = __float_as_uint(As_l[tig * 132 + r]);
            al[mt][1] = __float_as_uint(As_l[tig * 132 + r + 8]);
            al[mt][2] = __float_as_uint(As_l[(tig + 4) * 132 + r]);
            al[mt][3] = __float_as_uint(As_l[(tig + 4) * 132 + r + 8]);
        }
#pragma unroll
        for (int nt = 0; nt < 8; nt++) {
            const int cn = n0 + nt * 8;
            uint32_t bh0 = __float_as_uint(Bs_h[tig * 132 + cn]);
            uint32_t bh1 = __float_as_uint(Bs_h[(tig + 4) * 132 + cn]);
            uint32_t bl0 = __float_as_uint(Bs_l[tig * 132 + cn]);
            uint32_t bl1 = __float_as_uint(Bs_l[(tig + 4) * 132 + cn]);
#pragma unroll
            for (int mt = 0; mt < 2; mt++) {
                mma_tf32(acc[mt][nt], al[mt], bh0, bh1);
                mma_tf32(acc[mt][nt], ah[mt], bl0, bl1);
                mma_tf32(acc[mt][nt], ah[mt], bh0, bh1);
            }
        }

        if (kc + 1 < kchunks)
            stage_chunk(gsm + ((kc + 1) & 1) * GST, av, bv, ldr, ldk);
        __syncthreads();
    }
}

// ---------------------------------------------------------------------------
// Per-module XP GEMM: XP_m = x(strided t = k<<m) @ Wih[m-block]^T
// grid = (1, 1024>>m), K = 256.
// ---------------------------------------------------------------------------
__global__ __launch_bounds__(256, 2)
void gemm_xp1(const float* __restrict__ X, const float* __restrict__ Wih, int m)
{
    extern __shared__ float gsm[];
    const int tid = threadIdx.x;
    const int wid = tid >> 5;
    const int lane = tid & 31;
    const int grp = lane >> 2;
    const int tig = lane & 3;
    const int warpRow = wid >> 1;
    const int warpCol = wid & 1;
    const int ldr = tid >> 1;
    const int ldk = (tid & 1) << 2;
    const int ty = blockIdx.y;

    const int rowg = ty * 128 + ldr;
    const int bb = rowg & 63;
    const int kk = rowg >> 6;
    const float* Ag = X + ((size_t)bb * 2048 + ((size_t)kk << m)) * 256 + ldk;
    const float* Bg = Wih + ((size_t)(128 * m + ldr)) * 256 + ldk;

    float4 acc[2][8];
#pragma unroll
    for (int i = 0; i < 2; i++)
#pragma unroll
        for (int j = 0; j < 8; j++) acc[i][j] = make_float4(0.f, 0.f, 0.f, 0.f);

    gemm_core(Ag, Bg, 32, gsm, ldr, ldk, warpRow * 32 + grp, warpCol * 64 + grp, tig, acc);

    float* C = g_xp + xpoff(m);
#pragma unroll
    for (int nt = 0; nt < 8; nt++) {
        const int col = warpCol * 64 + nt * 8 + tig * 2;
#pragma unroll
        for (int mt = 0; mt < 2; mt++) {
            const int r0 = ty * 128 + warpRow * 32 + mt * 16 + grp;
            float4 d = acc[mt][nt];
            *(float2*)(C + (size_t)r0 * 128 + col)       = make_float2(d.x, d.y);
            *(float2*)(C + (size_t)(r0 + 8) * 128 + col) = make_float2(d.z, d.w);
        }
    }
}

// ---------------------------------------------------------------------------
// U-only GEMM for module j: U_j = ht_j @ Whh[0:128j, j-block]^T
// grid = (j, 1024>>j). K = 128.
// ---------------------------------------------------------------------------
__global__ __launch_bounds__(256, 2)
void gemm_u(const float* __restrict__ A, const float* __restrict__ B1,
            float* __restrict__ C1, int ldc1)
{
    extern __shared__ float gsm[];
    const int bn = blockIdx.x;
    const int bm = blockIdx.y;
    const int tid = threadIdx.x;
    const int wid = tid >> 5;
    const int lane = tid & 31;
    const int grp = lane >> 2;
    const int tig = lane & 3;
    const int warpRow = wid >> 1;
    const int warpCol = wid & 1;
    const int ldr = tid >> 1;
    const int ldk = (tid & 1) << 2;

    const float* Ag = A + (size_t)(bm * 128 + ldr) * 128 + ldk;
    const float* Bg = B1 + (size_t)(bn * 128 + ldr) * 1024 + ldk;

    float4 acc[2][8];
#pragma unroll
    for (int i = 0; i < 2; i++)
#pragma unroll
        for (int j = 0; j < 8; j++) acc[i][j] = make_float4(0.f, 0.f, 0.f, 0.f);

    gemm_core(Ag, Bg, 16, gsm, ldr, ldk, warpRow * 32 + grp, warpCol * 64 + grp, tig, acc);

#pragma unroll
    for (int nt = 0; nt < 8; nt++) {
        const int col = bn * 128 + warpCol * 64 + nt * 8 + tig * 2;
#pragma unroll
        for (int mt = 0; mt < 2; mt++) {
            const int r0 = bm * 128 + warpRow * 32 + mt * 16 + grp;
            float4 d = acc[mt][nt];
            *(float2*)(C1 + (size_t)r0 * ldc1 + col)       = make_float2(d.x, d.y);
            *(float2*)(C1 + (size_t)(r0 + 8) * ldc1 + col) = make_float2(d.z, d.w);
        }
    }
}

// ---------------------------------------------------------------------------
// Per-module C GEMM: C_m = ht_m @ fcw[:, m-block]^T. grid = (2, 1024>>m), K=128.
// ---------------------------------------------------------------------------
__global__ __launch_bounds__(256, 2)
void gemm_c1(const float* __restrict__ fcw, int m)
{
    extern __shared__ float gsm[];
    const int bn = blockIdx.x;
    const int ty = blockIdx.y;
    const int tid = threadIdx.x;
    const int wid = tid >> 5;
    const int lane = tid & 31;
    const int grp = lane >> 2;
    const int tig = lane & 3;
    const int warpRow = wid >> 1;
    const int warpCol = wid & 1;
    const int ldr = tid >> 1;
    const int ldk = (tid & 1) << 2;

    const float* Ag = g_ht + xpoff(m) + (size_t)(ty * 128 + ldr) * 128 + ldk;
    const float* Bg = fcw + 128 * m + (size_t)(bn * 128 + ldr) * 1024 + ldk;

    float4 acc[2][8];
#pragma unroll
    for (int i = 0; i < 2; i++)
#pragma unroll
        for (int j = 0; j < 8; j++) acc[i][j] = make_float4(0.f, 0.f, 0.f, 0.f);

    gemm_core(Ag, Bg, 16, gsm, ldr, ldk, warpRow * 32 + grp, warpCol * 64 + grp, tig, acc);

    float* C = g_c + coff(m);
#pragma unroll
    for (int nt = 0; nt < 8; nt++) {
        const int col = bn * 128 + warpCol * 64 + nt * 8 + tig * 2;
#pragma unroll
        for (int mt = 0; mt < 2; mt++) {
            const int r0 = ty * 128 + warpRow * 32 + mt * 16 + grp;
            float4 d = acc[mt][nt];
            *(float2*)(C + (size_t)r0 * 256 + col)       = make_float2(d.x, d.y);
            *(float2*)(C + (size_t)(r0 + 8) * 256 + col) = make_float2(d.z, d.w);
        }
    }
}

// ---------------------------------------------------------------------------
// Packed f32x2 helpers (FFMA2 — only reachable via PTX fma.rn.f32x2)
// ---------------------------------------------------------------------------
__device__ __forceinline__ unsigned long long fma2_(unsigned long long a,
                                                    unsigned long long b,
                                                    unsigned long long c) {
    unsigned long long d;
    asm("fma.rn.f32x2 %0, %1, %2, %3;" : "=l"(d) : "l"(a), "l"(b), "l"(c));
    return d;
}
__device__ __forceinline__ unsigned long long add2_(unsigned long long a,
                                                    unsigned long long b) {
    unsigned long long d;
    asm("add.rn.f32x2 %0, %1, %2;" : "=l"(d) : "l"(a), "l"(b));
    return d;
}

// ---------------------------------------------------------------------------
// Chain kernel: 128-dim sequential recurrence, TWO batch elements per CTA.
// 256 threads = 2 independent 128-thread groups (grp = tid>>7), one batch
// each, running in lockstep. 2 warps/SMSP -> latency segments of one group
// hide under the other's issue. Per-group state: hbuf[grp][2][128].
// Same proven FMA2 dot + distance-4 prefetch as R12/R14.
// ---------------------------------------------------------------------------
template<int MM>
__global__ __launch_bounds__(256, 1)
void chain_kernel(const float* __restrict__ Whh, const float* __restrict__ bih,
                  const float* __restrict__ bhh)
{
    constexpr int KS  = 2048 >> MM;
    constexpr int NU  = 7 - MM;
    constexpr int NUX = (NU > 0) ? NU : 1;

    const int tid = threadIdx.x;
    const int grp = tid >> 7;                    // 0 or 1: batch sub-group
    const int r   = tid & 127;                   // output row within module
    const int b   = blockIdx.x * 2 + grp;        // batch element

    // pinned full W row as 64 packed u64 (shared weights; same for both groups)
    unsigned long long w[64];
    {
        const float4* wrow = (const float4*)(Whh + (size_t)(128 * MM + r) * 1024 + 128 * MM);
#pragma unroll
        for (int q = 0; q < 32; q++) {
            float4 v = __ldg(wrow + q);
            union { float2 f; unsigned long long u; } c0, c1;
            c0.f = make_float2(v.x, v.y);
            c1.f = make_float2(v.z, v.w);
            w[2 * q]     = c0.u;
            w[2 * q + 1] = c1.u;
        }
    }

    const float bsr = __ldg(bih + 128 * MM + r) + __ldg(bhh + 128 * MM + r);

    __shared__ __align__(16) float hbuf[2][2][128];   // [grp][buf][row]
    hbuf[grp][1][r] = 0.f;
    __syncthreads();

    const float* xp = g_xp + xpoff(MM) + (size_t)b * 128 + r;
    float* ht = g_ht + xpoff(MM) + (size_t)b * 128 + r;

    const float* ub[NUX];
#pragma unroll
    for (int e = 0; e < NU; e++) {
        const int j = MM + 1 + e;
        ub[e] = g_u + uoff(j) + (size_t)b * (128 * j) + 128 * MM + r;
    }

    float zx[4];
    float zu[4][NUX];
    zx[0] = __ldg(xp);
#pragma unroll
    for (int e = 0; e < NU; e++) zu[0][e] = 0.f;
#pragma unroll
    for (int s = 1; s < 4; s++) {
        zx[s] = __ldg(xp + (size_t)s * 8192);
#pragma unroll
        for (int e = 0; e < NU; e++) {
            const int j = MM + 1 + e;
            const int ti = (((s) << MM) - 1) >> j;
            zu[s][e] = __ldg(ub[e] + (size_t)ti * (size_t)(8192 * j));
        }
    }

#define CHAIN_STEP(K, S)                                                        \
    do {                                                                        \
        const int kk = (K);                                                     \
        float z = zx[S] + bsr;                                                  \
        if (kk > 0) {                                                           \
            _Pragma("unroll")                                                   \
            for (int e = 0; e < NU; e++) z += zu[S][e];                         \
        }                                                                       \
        if (kk + 4 < KS) {                                                      \
            zx[S] = __ldg(xp + (size_t)(kk + 4) * 8192);                        \
            _Pragma("unroll")                                                   \
            for (int e = 0; e < NU; e++) {                                      \
                const int j = MM + 1 + e;                                       \
                const int ti = (((kk + 4) << MM) - 1) >> j;                     \
                zu[S][e] = __ldg(ub[e] + (size_t)ti * (size_t)(8192 * j));      \
            }                                                                   \
        }                                                                       \
        const ulonglong2* h8 = (const ulonglong2*)hbuf[grp][(kk + 1) & 1];      \
        unsigned long long p0 = 0, p1 = 0, p2 = 0, p3 = 0;                      \
        unsigned long long p4 = 0, p5 = 0, p6 = 0, p7 = 0;                      \
        _Pragma("unroll")                                                       \
        for (int q = 0; q < 8; q++) {                                           \
            ulonglong2 hA = h8[q * 4 + 0];                                      \
            ulonglong2 hB = h8[q * 4 + 1];                                      \
            ulonglong2 hC = h8[q * 4 + 2];                                      \
            ulonglong2 hD = h8[q * 4 + 3];                                      \
            p0 = fma2_(w[q * 8 + 0], hA.x, p0);                                 \
            p1 = fma2_(w[q * 8 + 1], hA.y, p1);                                 \
            p2 = fma2_(w[q * 8 + 2], hB.x, p2);                                 \
            p3 = fma2_(w[q * 8 + 3], hB.y, p3);                                 \
            p4 = fma2_(w[q * 8 + 4], hC.x, p4);                                 \
            p5 = fma2_(w[q * 8 + 5], hC.y, p5);                                 \
            p6 = fma2_(w[q * 8 + 6], hD.x, p6);                                 \
            p7 = fma2_(w[q * 8 + 7], hD.y, p7);                                 \
        }                                                                       \
        unsigned long long s01 = add2_(p0, p1), s23 = add2_(p2, p3);            \
        unsigned long long s45 = add2_(p4, p5), s67 = add2_(p6, p7);            \
        unsigned long long sAll = add2_(add2_(s01, s23), add2_(s45, s67));      \
        union { float2 f; unsigned long long u; } fin;                          \
        fin.u = sAll;                                                           \
        float dot = fin.f.x + fin.f.y;                                          \
        float xz = z + dot;                                                     \
        float ex = __expf(2.f * xz);                                            \
        float hn = 1.f - __fdividef(2.f, ex + 1.f);                             \
        hbuf[grp][kk & 1][r] = hn;                                              \
        ht[(size_t)kk * 8192] = hn;                                             \
        __syncthreads();                                                        \
    } while (0)

#pragma unroll 1
    for (int k = 0; k < KS; k += 4) {
        CHAIN_STEP(k,     0);
        CHAIN_STEP(k + 1, 1);
        CHAIN_STEP(k + 2, 2);
        CHAIN_STEP(k + 3, 3);
    }
#undef CHAIN_STEP
}

// ---------------------------------------------------------------------------
// Gather: y[b][t][i] = fc_b[i] + sum_m C_m[(t>>m)*64 + b][i]
// ---------------------------------------------------------------------------
__global__ __launch_bounds__(256)
void gather_y(const float* __restrict__ fcb, float* __restrict__ out)
{
    const int i = threadIdx.x;
    const float bias = __ldg(fcb + i);
#pragma unroll 1
    for (int e = 0; e < 8; e++) {
        const int tb = blockIdx.x * 8 + e;
        const int t = tb >> 6;
        const int b = tb & 63;
        float v = bias;
#pragma unroll
        for (int m = 0; m < 8; m++)
            v += g_c[coff(m) + (((size_t)((t >> m) * 64 + b)) << 8) + i];
        out[((size_t)b * 2048 + t) * 256 + i] = v;
    }
}

// ---------------------------------------------------------------------------
// Launch DAG with side stream (capture-safe ordering: every wait follows its
// record in host enqueue order). Serial fallback preserved.
// ---------------------------------------------------------------------------
static cudaStream_t g_s1 = 0;
static cudaEvent_t  g_evFork = 0, g_evSideEnd = 0;
static cudaEvent_t  g_evXP[8] = {0}, g_evChain[8] = {0};
static int g_streams_ok = -1;

static void init_streams_once()
{
    if (g_streams_ok != -1) return;
    g_streams_ok = 1;
    if (cudaStreamCreateWithFlags(&g_s1, cudaStreamNonBlocking) != cudaSuccess) {
        g_streams_ok = 0; return;
    }
    if (cudaEventCreateWithFlags(&g_evFork, cudaEventDisableTiming) != cudaSuccess ||
        cudaEventCreateWithFlags(&g_evSideEnd, cudaEventDisableTiming) != cudaSuccess) {
        g_streams_ok = 0; return;
    }
    for (int m = 0; m < 8; m++) {
        if (cudaEventCreateWithFlags(&g_evXP[m], cudaEventDisableTiming) != cudaSuccess ||
            cudaEventCreateWithFlags(&g_evChain[m], cudaEventDisableTiming) != cudaSuccess) {
            g_streams_ok = 0; return;
        }
    }
}

template<int J>
static void launch_chain(const float* whh, const float* bih, const float* bhh)
{
    chain_kernel<J><<<BATCH / 2, 256>>>(whh, bih, bhh);
}
typedef void (*chain_fn)(const float*, const float*, const float*);
static const chain_fn CHAINS[8] = {
    launch_chain<0>, launch_chain<1>, launch_chain<2>, launch_chain<3>,
    launch_chain<4>, launch_chain<5>, launch_chain<6>, launch_chain<7>
};

extern "C" void kernel_launch(void* const* d_in, const int* in_sizes, int n_in,
                              void* d_out, int out_size)
{
    const float* x   = (const float*)d_in[0];
    const float* wih = (const float*)d_in[1];
    const float* whh = (const float*)d_in[2];
    const float* bih = (const float*)d_in[3];
    const float* bhh = (const float*)d_in[4];
    const float* fcw = (const float*)d_in[5];
    const float* fcb = (const float*)d_in[6];
    float* out = (float*)d_out;

    void* p;
    cudaGetSymbolAddress(&p, g_ht); float* pht = (float*)p;
    cudaGetSymbolAddress(&p, g_u);  float* pu  = (float*)p;

    cudaFuncSetAttribute(gemm_xp1, cudaFuncAttributeMaxDynamicSharedMemorySize, GEMM_SMEM_BYTES);
    cudaFuncSetAttribute(gemm_u,   cudaFuncAttributeMaxDynamicSharedMemorySize, GEMM_SMEM_BYTES);
    cudaFuncSetAttribute(gemm_c1,  cudaFuncAttributeMaxDynamicSharedMemorySize, GEMM_SMEM_BYTES);

    init_streams_once();

    if (g_streams_ok) {
        cudaEventRecord(g_evFork, 0);
        cudaStreamWaitEvent(g_s1, g_evFork, 0);

        for (int m = 6; m >= 0; m--) {
            dim3 g(1, (unsigned)(1024 >> m));
            gemm_xp1<<<g, 256, GEMM_SMEM_BYTES, g_s1>>>(x, wih, m);
            cudaEventRecord(g_evXP[m], g_s1);
        }

        {
            dim3 g(1, 8);
            gemm_xp1<<<g, 256, GEMM_SMEM_BYTES>>>(x, wih, 7);
        }

        for (int j = 7; j >= 1; j--) {
            CHAINS[j](whh, bih, bhh);
            cudaEventRecord(g_evChain[j], 0);

            cudaStreamWaitEvent(g_s1, g_evChain[j], 0);
            {
                dim3 gc(2, (unsigned)(1024 >> j));
                gemm_c1<<<gc, 256, GEMM_SMEM_BYTES, g_s1>>>(fcw, j);
            }

            dim3 g((unsigned)j, (unsigned)(1024 >> j));
            gemm_u<<<g, 256, GEMM_SMEM_BYTES>>>(
                pht + xpoff(j), whh + 128 * j, pu + uoff(j), 128 * j);
            cudaStreamWaitEvent(0, g_evXP[j - 1], 0);
        }

        CHAINS[0](whh, bih, bhh);
        cudaEventRecord(g_evChain[0], 0);

        cudaStreamWaitEvent(g_s1, g_evChain[0], 0);
        {
            dim3 gc(2, 1024);
            gemm_c1<<<gc, 256, GEMM_SMEM_BYTES, g_s1>>>(fcw, 0);
        }
        cudaEventRecord(g_evSideEnd, g_s1);

        cudaStreamWaitEvent(0, g_evSideEnd, 0);
        gather_y<<<16384, 256>>>(fcb, out);
    } else {
        for (int m = 7; m >= 0; m--) {
            dim3 g(1, (unsigned)(1024 >> m));
            gemm_xp1<<<g, 256, GEMM_SMEM_BYTES>>>(x, wih, m);
        }
        for (int j = 7; j >= 1; j--) {
            CHAINS[j](whh, bih, bhh);
            dim3 g((unsigned)j, (unsigned)(1024 >> j));
            gemm_u<<<g, 256, GEMM_SMEM_BYTES>>>(
                pht + xpoff(j), whh + 128 * j, pu + uoff(j), 128 * j);
        }
        CHAINS[0](whh, bih, bhh);
        for (int m = 7; m >= 0; m--) {
            dim3 g(2, (unsigned)(1024 >> m));
            gemm_c1<<<g, 256, GEMM_SMEM_BYTES>>>(fcw, m);
        }
        gather_y<<<16384, 256>>>(fcb, out);
    }
}

// round 16
// speedup vs baseline: 1.2487x; 1.2487x over previous
#include <cuda_runtime.h>
#include <math.h>
#include <stdint.h>

#define BATCH 64
#define SEQT  2048
#define ISZ   256
#define HSZ   1024

// ---------------------------------------------------------------------------
// Global scratch (module-compact layouts).
//  XP_m[k][b][128] : input projection at module-m active times (t = k<<m)
//  HT_m[k][b][128] : module-m hidden trajectory samples
//  U_j [k][b][128j]: Whh[0:128j, j-block] @ h_j^(k)
//  C_m [k][b][256] : fc_w[:, m-block] @ h_m^(k)
//  g_flag[b]       : producer progress for U_1 (chain1u -> chain0w)
// ---------------------------------------------------------------------------
#define XP_TOT 33423360ull
#define U_TOT  32374784ull
#define C_TOT  66846720ull
static __device__ float g_xp[XP_TOT];
static __device__ float g_ht[XP_TOT];
static __device__ float g_u [U_TOT];
static __device__ float g_c [C_TOT];
static __device__ int   g_flag[BATCH];

__host__ __device__ constexpr size_t xpoff(int m) {
    return 8192ull * (size_t)(4096 - (4096 >> m));
}
__host__ __device__ constexpr size_t uoff(int j) {
    size_t s = 0;
    for (int p = 1; p < j; p++) s += (size_t)(2048 >> p) * 8192ull * (size_t)p;
    return s;
}
__host__ __device__ constexpr size_t coff(int m) {
    return 16384ull * (size_t)(4096 - (4096 >> m));
}

// ---------------------------------------------------------------------------
// TF32 3-split GEMM core (fp32-accurate)
// ---------------------------------------------------------------------------
__device__ __forceinline__ uint32_t f32_to_tf32(float x) {
    uint32_t r;
    asm("cvt.rna.tf32.f32 %0, %1;" : "=r"(r) : "f"(x));
    return r;
}
__device__ __forceinline__ void mma_tf32(float4& d, const uint32_t a[4],
                                         const uint32_t b0, const uint32_t b1) {
    asm volatile(
        "mma.sync.aligned.m16n8k8.row.col.f32.tf32.tf32.f32 "
        "{%0,%1,%2,%3}, {%4,%5,%6,%7}, {%8,%9}, {%0,%1,%2,%3};"
        : "+f"(d.x), "+f"(d.y), "+f"(d.z), "+f"(d.w)
        : "r"(a[0]), "r"(a[1]), "r"(a[2]), "r"(a[3]), "r"(b0), "r"(b1));
}

#define GST 4224
#define GEMM_SMEM_BYTES (2 * GST * 4)

__device__ __forceinline__ void stage_chunk(float* s, const float4 av, const float4 bv,
                                            int ldr, int ldk)
{
    const float a4[4] = {av.x, av.y, av.z, av.w};
    const float b4[4] = {bv.x, bv.y, bv.z, bv.w};
#pragma unroll
    for (int e = 0; e < 4; e++) {
        uint32_t hi = f32_to_tf32(a4[e]);
        float lo = a4[e] - __uint_as_float(hi);
        s[(ldk + e) * 132 + ldr]        = __uint_as_float(hi);
        s[1056 + (ldk + e) * 132 + ldr] = __uint_as_float(f32_to_tf32(lo));
        uint32_t bhi = f32_to_tf32(b4[e]);
        float blo = b4[e] - __uint_as_float(bhi);
        s[2112 + (ldk + e) * 132 + ldr] = __uint_as_float(bhi);
        s[3168 + (ldk + e) * 132 + ldr] = __uint_as_float(f32_to_tf32(blo));
    }
}

__device__ __forceinline__ void gemm_core(const float* Ag, const float* Bg,
                                          int kchunks, float* gsm,
                                          int ldr, int ldk, int m0, int n0, int tig,
                                          float4 acc[2][8])
{
    stage_chunk(gsm, *(const float4*)Ag, *(const float4*)Bg, ldr, ldk);
    __syncthreads();

    for (int kc = 0; kc < kchunks; kc++) {
        float4 av, bv;
        if (kc + 1 < kchunks) {
            av = *(const float4*)(Ag + (kc + 1) * 8);
            bv = *(const float4*)(Bg + (kc + 1) * 8);
        }
        const float* As_h = gsm + (kc & 1) * GST;
        const float* As_l = As_h + 1056;
        const float* Bs_h = As_h + 2112;
        const float* Bs_l = As_h + 3168;

        uint32_t ah[2][4], al[2][4];
#pragma unroll
        for (int mt = 0; mt < 2; mt++) {
            const int r = m0 + mt * 16;
            ah[mt][0] = __float_as_uint(As_h[tig * 132 + r]);
            ah[mt][1] = __float_as_uint(As_h[tig * 132 + r + 8]);
            ah[mt][2] = __float_as_uint(As_h[(tig + 4) * 132 + r]);
            ah[mt][3] = __float_as_uint(As_h[(tig + 4) * 132 + r + 8]);
            al[mt][0] = __float_as_uint(As_l[tig * 132 + r]);
            al[mt][1] = __float_as_uint(As_l[tig * 132 + r + 8]);
            al[mt][2] = __float_as_uint(As_l[(tig + 4) * 132 + r]);
            al[mt][3] = __float_as_uint(As_l[(tig + 4) * 132 + r + 8]);
        }
#pragma unroll
        for (int nt = 0; nt < 8; nt++) {
            const int cn = n0 + nt * 8;
            uint32_t bh0 = __float_as_uint(Bs_h[tig * 132 + cn]);
            uint32_t bh1 = __float_as_uint(Bs_h[(tig + 4) * 132 + cn]);
            uint32_t bl0 = __float_as_uint(Bs_l[tig * 132 + cn]);
            uint32_t bl1 = __float_as_uint(Bs_l[(tig + 4) * 132 + cn]);
#pragma unroll
            for (int mt = 0; mt < 2; mt++) {
                mma_tf32(acc[mt][nt], al[mt], bh0, bh1);
                mma_tf32(acc[mt][nt], ah[mt], bl0, bl1);
                mma_tf32(acc[mt][nt], ah[mt], bh0, bh1);
            }
        }

        if (kc + 1 < kchunks)
            stage_chunk(gsm + ((kc + 1) & 1) * GST, av, bv, ldr, ldk);
        __syncthreads();
    }
}

// ---------------------------------------------------------------------------
// Per-module XP GEMM: grid = (1, 1024>>m), K = 256.
// ---------------------------------------------------------------------------
__global__ __launch_bounds__(256, 2)
void gemm_xp1(const float* __restrict__ X, const float* __restrict__ Wih, int m)
{
    extern __shared__ float gsm[];
    const int tid = threadIdx.x;
    const int wid = tid >> 5;
    const int lane = tid & 31;
    const int grp = lane >> 2;
    const int tig = lane & 3;
    const int warpRow = wid >> 1;
    const int warpCol = wid & 1;
    const int ldr = tid >> 1;
    const int ldk = (tid & 1) << 2;
    const int ty = blockIdx.y;

    const int rowg = ty * 128 + ldr;
    const int bb = rowg & 63;
    const int kk = rowg >> 6;
    const float* Ag = X + ((size_t)bb * 2048 + ((size_t)kk << m)) * 256 + ldk;
    const float* Bg = Wih + ((size_t)(128 * m + ldr)) * 256 + ldk;

    float4 acc[2][8];
#pragma unroll
    for (int i = 0; i < 2; i++)
#pragma unroll
        for (int j = 0; j < 8; j++) acc[i][j] = make_float4(0.f, 0.f, 0.f, 0.f);

    gemm_core(Ag, Bg, 32, gsm, ldr, ldk, warpRow * 32 + grp, warpCol * 64 + grp, tig, acc);

    float* C = g_xp + xpoff(m);
#pragma unroll
    for (int nt = 0; nt < 8; nt++) {
        const int col = warpCol * 64 + nt * 8 + tig * 2;
#pragma unroll
        for (int mt = 0; mt < 2; mt++) {
            const int r0 = ty * 128 + warpRow * 32 + mt * 16 + grp;
            float4 d = acc[mt][nt];
            *(float2*)(C + (size_t)r0 * 128 + col)       = make_float2(d.x, d.y);
            *(float2*)(C + (size_t)(r0 + 8) * 128 + col) = make_float2(d.z, d.w);
        }
    }
}

// ---------------------------------------------------------------------------
// U-only GEMM for module j (j >= 2 now): grid = (j, 1024>>j). K = 128.
// ---------------------------------------------------------------------------
__global__ __launch_bounds__(256, 2)
void gemm_u(const float* __restrict__ A, const float* __restrict__ B1,
            float* __restrict__ C1, int ldc1)
{
    extern __shared__ float gsm[];
    const int bn = blockIdx.x;
    const int bm = blockIdx.y;
    const int tid = threadIdx.x;
    const int wid = tid >> 5;
    const int lane = tid & 31;
    const int grp = lane >> 2;
    const int tig = lane & 3;
    const int warpRow = wid >> 1;
    const int warpCol = wid & 1;
    const int ldr = tid >> 1;
    const int ldk = (tid & 1) << 2;

    const float* Ag = A + (size_t)(bm * 128 + ldr) * 128 + ldk;
    const float* Bg = B1 + (size_t)(bn * 128 + ldr) * 1024 + ldk;

    float4 acc[2][8];
#pragma unroll
    for (int i = 0; i < 2; i++)
#pragma unroll
        for (int j = 0; j < 8; j++) acc[i][j] = make_float4(0.f, 0.f, 0.f, 0.f);

    gemm_core(Ag, Bg, 16, gsm, ldr, ldk, warpRow * 32 + grp, warpCol * 64 + grp, tig, acc);

#pragma unroll
    for (int nt = 0; nt < 8; nt++) {
        const int col = bn * 128 + warpCol * 64 + nt * 8 + tig * 2;
#pragma unroll
        for (int mt = 0; mt < 2; mt++) {
            const int r0 = bm * 128 + warpRow * 32 + mt * 16 + grp;
            float4 d = acc[mt][nt];
            *(float2*)(C1 + (size_t)r0 * ldc1 + col)       = make_float2(d.x, d.y);
            *(float2*)(C1 + (size_t)(r0 + 8) * ldc1 + col) = make_float2(d.z, d.w);
        }
    }
}

// ---------------------------------------------------------------------------
// Per-module C GEMM: grid = (2, 1024>>m), K = 128.
// ---------------------------------------------------------------------------
__global__ __launch_bounds__(256, 2)
void gemm_c1(const float* __restrict__ fcw, int m)
{
    extern __shared__ float gsm[];
    const int bn = blockIdx.x;
    const int ty = blockIdx.y;
    const int tid = threadIdx.x;
    const int wid = tid >> 5;
    const int lane = tid & 31;
    const int grp = lane >> 2;
    const int tig = lane & 3;
    const int warpRow = wid >> 1;
    const int warpCol = wid & 1;
    const int ldr = tid >> 1;
    const int ldk = (tid & 1) << 2;

    const float* Ag = g_ht + xpoff(m) + (size_t)(ty * 128 + ldr) * 128 + ldk;
    const float* Bg = fcw + 128 * m + (size_t)(bn * 128 + ldr) * 1024 + ldk;

    float4 acc[2][8];
#pragma unroll
    for (int i = 0; i < 2; i++)
#pragma unroll
        for (int j = 0; j < 8; j++) acc[i][j] = make_float4(0.f, 0.f, 0.f, 0.f);

    gemm_core(Ag, Bg, 16, gsm, ldr, ldk, warpRow * 32 + grp, warpCol * 64 + grp, tig, acc);

    float* C = g_c + coff(m);
#pragma unroll
    for (int nt = 0; nt < 8; nt++) {
        const int col = bn * 128 + warpCol * 64 + nt * 8 + tig * 2;
#pragma unroll
        for (int mt = 0; mt < 2; mt++) {
            const int r0 = ty * 128 + warpRow * 32 + mt * 16 + grp;
            float4 d = acc[mt][nt];
            *(float2*)(C + (size_t)r0 * 256 + col)       = make_float2(d.x, d.y);
            *(float2*)(C + (size_t)(r0 + 8) * 256 + col) = make_float2(d.z, d.w);
        }
    }
}

// ---------------------------------------------------------------------------
// Packed f32x2 + acquire/release helpers
// ---------------------------------------------------------------------------
__device__ __forceinline__ unsigned long long fma2_(unsigned long long a,
                                                    unsigned long long b,
                                                    unsigned long long c) {
    unsigned long long d;
    asm("fma.rn.f32x2 %0, %1, %2, %3;" : "=l"(d) : "l"(a), "l"(b), "l"(c));
    return d;
}
__device__ __forceinline__ unsigned long long add2_(unsigned long long a,
                                                    unsigned long long b) {
    unsigned long long d;
    asm("add.rn.f32x2 %0, %1, %2;" : "=l"(d) : "l"(a), "l"(b));
    return d;
}
__device__ __forceinline__ int ld_acq(const int* p) {
    int v;
    asm volatile("ld.acquire.gpu.global.s32 %0, [%1];" : "=r"(v) : "l"(p) : "memory");
    return v;
}
__device__ __forceinline__ void st_rel(int* p, int v) {
    asm volatile("st.release.gpu.global.s32 [%0], %1;" :: "l"(p), "r"(v) : "memory");
}

// full 128-wide packed dot of pinned w[64] against hbuf row set
__device__ __forceinline__ float dot128(const unsigned long long* w, const float* hrow)
{
    const ulonglong2* h8 = (const ulonglong2*)hrow;
    unsigned long long p0 = 0, p1 = 0, p2 = 0, p3 = 0;
    unsigned long long p4 = 0, p5 = 0, p6 = 0, p7 = 0;
#pragma unroll
    for (int q = 0; q < 8; q++) {
        ulonglong2 hA = h8[q * 4 + 0];
        ulonglong2 hB = h8[q * 4 + 1];
        ulonglong2 hC = h8[q * 4 + 2];
        ulonglong2 hD = h8[q * 4 + 3];
        p0 = fma2_(w[q * 8 + 0], hA.x, p0);
        p1 = fma2_(w[q * 8 + 1], hA.y, p1);
        p2 = fma2_(w[q * 8 + 2], hB.x, p2);
        p3 = fma2_(w[q * 8 + 3], hB.y, p3);
        p4 = fma2_(w[q * 8 + 4], hC.x, p4);
        p5 = fma2_(w[q * 8 + 5], hC.y, p5);
        p6 = fma2_(w[q * 8 + 6], hD.x, p6);
        p7 = fma2_(w[q * 8 + 7], hD.y, p7);
    }
    unsigned long long s01 = add2_(p0, p1), s23 = add2_(p2, p3);
    unsigned long long s45 = add2_(p4, p5), s67 = add2_(p6, p7);
    unsigned long long sAll = add2_(add2_(s01, s23), add2_(s45, s67));
    union { float2 f; unsigned long long u; } fin;
    fin.u = sAll;
    return fin.f.x + fin.f.y;
}
__device__ __forceinline__ void load_wrow(unsigned long long* w, const float4* wrow)
{
#pragma unroll
    for (int q = 0; q < 32; q++) {
        float4 v = __ldg(wrow + q);
        union { float2 f; unsigned long long u; } c0, c1;
        c0.f = make_float2(v.x, v.y);
        c1.f = make_float2(v.z, v.w);
        w[2 * q]     = c0.u;
        w[2 * q + 1] = c1.u;
    }
}
__device__ __forceinline__ float ftanh(float z)
{
    float ex = __expf(2.f * z);
    return 1.f - __fdividef(2.f, ex + 1.f);
}

// ---------------------------------------------------------------------------
// Chain kernel (modules 7..2): proven R12/R14 structure, 128 threads.
// ---------------------------------------------------------------------------
template<int MM>
__global__ __launch_bounds__(128, 1)
void chain_kernel(const float* __restrict__ Whh, const float* __restrict__ bih,
                  const float* __restrict__ bhh)
{
    constexpr int KS  = 2048 >> MM;
    constexpr int NU  = 7 - MM;
    constexpr int NUX = (NU > 0) ? NU : 1;

    const int b = blockIdx.x;
    const int r = threadIdx.x;

    unsigned long long w[64];
    load_wrow(w, (const float4*)(Whh + (size_t)(128 * MM + r) * 1024 + 128 * MM));

    const float bsr = __ldg(bih + 128 * MM + r) + __ldg(bhh + 128 * MM + r);

    __shared__ __align__(16) float hbuf[2][128];
    hbuf[1][r] = 0.f;
    __syncthreads();

    const float* xp = g_xp + xpoff(MM) + (size_t)b * 128 + r;
    float* ht = g_ht + xpoff(MM) + (size_t)b * 128 + r;

    const float* ub[NUX];
#pragma unroll
    for (int e = 0; e < NU; e++) {
        const int j = MM + 1 + e;
        ub[e] = g_u + uoff(j) + (size_t)b * (128 * j) + 128 * MM + r;
    }

    float zx[4];
    float zu[4][NUX];
    zx[0] = __ldg(xp);
#pragma unroll
    for (int e = 0; e < NU; e++) zu[0][e] = 0.f;
#pragma unroll
    for (int s = 1; s < 4; s++) {
        zx[s] = __ldg(xp + (size_t)s * 8192);
#pragma unroll
        for (int e = 0; e < NU; e++) {
            const int j = MM + 1 + e;
            const int ti = (((s) << MM) - 1) >> j;
            zu[s][e] = __ldg(ub[e] + (size_t)ti * (size_t)(8192 * j));
        }
    }

#define CHAIN_STEP(K, S)                                                        \
    do {                                                                        \
        const int kk = (K);                                                     \
        float z = zx[S] + bsr;                                                  \
        if (kk > 0) {                                                           \
            _Pragma("unroll")                                                   \
            for (int e = 0; e < NU; e++) z += zu[S][e];                         \
        }                                                                       \
        if (kk + 4 < KS) {                                                      \
            zx[S] = __ldg(xp + (size_t)(kk + 4) * 8192);                        \
            _Pragma("unroll")                                                   \
            for (int e = 0; e < NU; e++) {                                      \
                const int j = MM + 1 + e;                                       \
                const int ti = (((kk + 4) << MM) - 1) >> j;                     \
                zu[S][e] = __ldg(ub[e] + (size_t)ti * (size_t)(8192 * j));      \
            }                                                                   \
        }                                                                       \
        float dot = dot128(w, hbuf[(kk + 1) & 1]);                              \
        float hn = ftanh(z + dot);                                              \
        hbuf[kk & 1][r] = hn;                                                   \
        ht[(size_t)kk * 8192] = hn;                                             \
        __syncthreads();                                                        \
    } while (0)

#pragma unroll 1
    for (int k = 0; k < KS; k += 4) {
        CHAIN_STEP(k,     0);
        CHAIN_STEP(k + 1, 1);
        CHAIN_STEP(k + 2, 2);
        CHAIN_STEP(k + 3, 3);
    }
#undef CHAIN_STEP
}

// ---------------------------------------------------------------------------
// chain1u: module 1 chain + inline U_1 producer. 256 threads:
//   group A (tid<128): module-1 recurrence (identical to chain_kernel<1>)
//   group B (tid>=128): one step behind, computes U_1[k-1] = W01 @ h_1^{k-1},
//     publishes per-batch progress flag with release semantics.
// ---------------------------------------------------------------------------
__global__ __launch_bounds__(256, 1)
void chain1u(const float* __restrict__ Whh, const float* __restrict__ bih,
             const float* __restrict__ bhh)
{
    constexpr int MM = 1;
    constexpr int KS = 1024;
    constexpr int NU = 6;

    const int tid = threadIdx.x;
    const int grp = tid >> 7;
    const int r   = tid & 127;
    const int b   = blockIdx.x;

    // A: module-1 diagonal rows (128+r, cols 128..255). B: U_1 rows (r, cols 128..255).
    unsigned long long w[64];
    load_wrow(w, (const float4*)(Whh + (size_t)((grp == 0 ? 128 + r : r)) * 1024 + 128));

    float bsr = 0.f;
    if (grp == 0) bsr = __ldg(bih + 128 + r) + __ldg(bhh + 128 + r);

    __shared__ __align__(16) float hbuf[2][128];
    if (grp == 0) hbuf[1][r] = 0.f;
    __syncthreads();

    const float* xp = g_xp + xpoff(1) + (size_t)b * 128 + r;
    float* ht = g_ht + xpoff(1) + (size_t)b * 128 + r;
    float* uout = g_u + uoff(1) + (size_t)b * 128 + r;   // + k*8192
    int* flagp = g_flag + b;

    const float* ub[NU];
    float zx[4];
    float zu[4][NU];
    if (grp == 0) {
#pragma unroll
        for (int e = 0; e < NU; e++) {
            const int j = 2 + e;
            ub[e] = g_u + uoff(j) + (size_t)b * (128 * j) + 128 + r;
        }
        zx[0] = __ldg(xp);
#pragma unroll
        for (int e = 0; e < NU; e++) zu[0][e] = 0.f;
#pragma unroll
        for (int s = 1; s < 4; s++) {
            zx[s] = __ldg(xp + (size_t)s * 8192);
#pragma unroll
            for (int e = 0; e < NU; e++) {
                const int j = 2 + e;
                const int ti = ((s << 1) - 1) >> j;
                zu[s][e] = __ldg(ub[e] + (size_t)ti * (size_t)(8192 * j));
            }
        }
    }

#define C1_STEP(K, S)                                                           \
    do {                                                                        \
        const int kk = (K);                                                     \
        if (grp == 0) {                                                         \
            float z = zx[S] + bsr;                                              \
            if (kk > 0) {                                                       \
                _Pragma("unroll")                                               \
                for (int e = 0; e < NU; e++) z += zu[S][e];                     \
            }                                                                   \
            if (kk + 4 < KS) {                                                  \
                zx[S] = __ldg(xp + (size_t)(kk + 4) * 8192);                    \
                _Pragma("unroll")                                               \
                for (int e = 0; e < NU; e++) {                                  \
                    const int j = 2 + e;                                        \
                    const int ti = (((kk + 4) << 1) - 1) >> j;                  \
                    zu[S][e] = __ldg(ub[e] + (size_t)ti * (size_t)(8192 * j));  \
                }                                                               \
            }                                                                   \
            float dot = dot128(w, hbuf[(kk + 1) & 1]);                          \
            float hn = ftanh(z + dot);                                          \
            hbuf[kk & 1][r] = hn;                                               \
            ht[(size_t)kk * 8192] = hn;                                         \
        } else {                                                                \
            if (r == 0 && kk >= 2) st_rel(flagp, kk - 1);                       \
            const int sp = kk - 1;                                              \
            if (sp >= 0) {                                                      \
                float dv = dot128(w, hbuf[sp & 1]);                             \
                uout[(size_t)sp * 8192] = dv;                                   \
            }                                                                   \
        }                                                                       \
        __syncthreads();                                                        \
    } while (0)

#pragma unroll 1
    for (int k = 0; k < KS; k += 4) {
        C1_STEP(k,     0);
        C1_STEP(k + 1, 1);
        C1_STEP(k + 2, 2);
        C1_STEP(k + 3, 3);
    }
#undef C1_STEP

    // tail: B computes the final sample (KS-1), then publishes full count.
    if (grp == 1) {
        float dv = dot128(w, hbuf[(KS - 1) & 1]);
        uout[(size_t)(KS - 1) * 8192] = dv;
    }
    __syncthreads();
    if (tid == 128) st_rel(flagp, KS);
}

// ---------------------------------------------------------------------------
// chain0w: module 0 chain; U_1 reads gated on the producer flag (acquire).
// ---------------------------------------------------------------------------
__global__ __launch_bounds__(128, 1)
void chain0w(const float* __restrict__ Whh, const float* __restrict__ bih,
             const float* __restrict__ bhh)
{
    constexpr int KS = 2048;
    constexpr int NU = 7;

    const int b = blockIdx.x;
    const int r = threadIdx.x;

    unsigned long long w[64];
    load_wrow(w, (const float4*)(Whh + (size_t)r * 1024));

    const float bsr = __ldg(bih + r) + __ldg(bhh + r);

    __shared__ __align__(16) float hbuf[2][128];
    hbuf[1][r] = 0.f;
    __syncthreads();

    const float* xp = g_xp + (size_t)b * 128 + r;
    float* ht = g_ht + (size_t)b * 128 + r;
    const int* flagp = g_flag + b;
    int known = 0;

    const float* ub[NU];
#pragma unroll
    for (int e = 0; e < NU; e++) {
        const int j = 1 + e;
        ub[e] = g_u + uoff(j) + (size_t)b * (128 * j) + r;
    }

    // initial prefetch needs U_1 up to ti=1 -> flag >= 2
    while (known < 2) known = ld_acq(flagp);

    float zx[4];
    float zu[4][NU];
    zx[0] = __ldg(xp);
#pragma unroll
    for (int e = 0; e < NU; e++) zu[0][e] = 0.f;
#pragma unroll
    for (int s = 1; s < 4; s++) {
        zx[s] = __ldg(xp + (size_t)s * 8192);
#pragma unroll
        for (int e = 0; e < NU; e++) {
            const int j = 1 + e;
            const int ti = (s - 1) >> j;
            zu[s][e] = __ldg(ub[e] + (size_t)ti * (size_t)(8192 * j));
        }
    }

#define C0_STEP(K, S)                                                           \
    do {                                                                        \
        const int kk = (K);                                                     \
        float z = zx[S] + bsr;                                                  \
        if (kk > 0) {                                                           \
            _Pragma("unroll")                                                   \
            for (int e = 0; e < NU; e++) z += zu[S][e];                         \
        }                                                                       \
        if (kk + 4 < KS) {                                                      \
            zx[S] = __ldg(xp + (size_t)(kk + 4) * 8192);                        \
            {   /* e = 0 (j = 1): gated on producer flag */                     \
                const int ti = (kk + 3) >> 1;                                   \
                if (ti + 1 > known) {                                           \
                    int f;                                                      \
                    do { f = ld_acq(flagp); } while (f < ti + 1);               \
                    known = f;                                                  \
                }                                                               \
                zu[S][0] = __ldg(ub[0] + (size_t)ti * 8192);                    \
            }                                                                   \
            _Pragma("unroll")                                                   \
            for (int e = 1; e < NU; e++) {                                      \
                const int j = 1 + e;                                            \
                const int ti = (kk + 3) >> j;                                   \
                zu[S][e] = __ldg(ub[e] + (size_t)ti * (size_t)(8192 * j));      \
            }                                                                   \
        }                                                                       \
        float dot = dot128(w, hbuf[(kk + 1) & 1]);                              \
        float hn = ftanh(z + dot);                                              \
        hbuf[kk & 1][r] = hn;                                                   \
        ht[(size_t)kk * 8192] = hn;                                             \
        __syncthreads();                                                        \
    } while (0)

#pragma unroll 1
    for (int k = 0; k < KS; k += 4) {
        C0_STEP(k,     0);
        C0_STEP(k + 1, 1);
        C0_STEP(k + 2, 2);
        C0_STEP(k + 3, 3);
    }
#undef C0_STEP
}

// ---------------------------------------------------------------------------
// zero flags (must run at the start of every replay)
// ---------------------------------------------------------------------------
__global__ void zero_flags()
{
    if (threadIdx.x < BATCH) g_flag[threadIdx.x] = 0;
}

// ---------------------------------------------------------------------------
// Gather: y[b][t][i] = fc_b[i] + sum_m C_m[(t>>m)*64 + b][i]
// ---------------------------------------------------------------------------
__global__ __launch_bounds__(256)
void gather_y(const float* __restrict__ fcb, float* __restrict__ out)
{
    const int i = threadIdx.x;
    const float bias = __ldg(fcb + i);
#pragma unroll 1
    for (int e = 0; e < 8; e++) {
        const int tb = blockIdx.x * 8 + e;
        const int t = tb >> 6;
        const int b = tb & 63;
        float v = bias;
#pragma unroll
        for (int m = 0; m < 8; m++)
            v += g_c[coff(m) + (((size_t)((t >> m) * 64 + b)) << 8) + i];
        out[((size_t)b * 2048 + t) * 256 + i] = v;
    }
}

// ---------------------------------------------------------------------------
// Launch DAG. chain1u (main) and chain0w (side) run CONCURRENTLY;
// chain0w consumes U_1 progressively via flags. All stream waits are
// enqueued after their event records (capture-safe). Serial fallback works
// because flags are complete before chain0w runs.
// ---------------------------------------------------------------------------
static cudaStream_t g_s1 = 0;
static cudaEvent_t  g_evFork = 0, g_evSideEnd = 0, g_evU2 = 0;
static cudaEvent_t  g_evXP[8] = {0}, g_evChain[8] = {0};
static int g_streams_ok = -1;

static void init_streams_once()
{
    if (g_streams_ok != -1) return;
    g_streams_ok = 1;
    if (cudaStreamCreateWithFlags(&g_s1, cudaStreamNonBlocking) != cudaSuccess) {
        g_streams_ok = 0; return;
    }
    if (cudaEventCreateWithFlags(&g_evFork, cudaEventDisableTiming) != cudaSuccess ||
        cudaEventCreateWithFlags(&g_evSideEnd, cudaEventDisableTiming) != cudaSuccess ||
        cudaEventCreateWithFlags(&g_evU2, cudaEventDisableTiming) != cudaSuccess) {
        g_streams_ok = 0; return;
    }
    for (int m = 0; m < 8; m++) {
        if (cudaEventCreateWithFlags(&g_evXP[m], cudaEventDisableTiming) != cudaSuccess ||
            cudaEventCreateWithFlags(&g_evChain[m], cudaEventDisableTiming) != cudaSuccess) {
            g_streams_ok = 0; return;
        }
    }
}

template<int J>
static void launch_chain(const float* whh, const float* bih, const float* bhh)
{
    chain_kernel<J><<<BATCH, 128>>>(whh, bih, bhh);
}
typedef void (*chain_fn)(const float*, const float*, const float*);
static const chain_fn CHAINS[8] = {
    0, 0, launch_chain<2>, launch_chain<3>,
    launch_chain<4>, launch_chain<5>, launch_chain<6>, launch_chain<7>
};

extern "C" void kernel_launch(void* const* d_in, const int* in_sizes, int n_in,
                              void* d_out, int out_size)
{
    const float* x   = (const float*)d_in[0];
    const float* wih = (const float*)d_in[1];
    const float* whh = (const float*)d_in[2];
    const float* bih = (const float*)d_in[3];
    const float* bhh = (const float*)d_in[4];
    const float* fcw = (const float*)d_in[5];
    const float* fcb = (const float*)d_in[6];
    float* out = (float*)d_out;

    void* p;
    cudaGetSymbolAddress(&p, g_ht); float* pht = (float*)p;
    cudaGetSymbolAddress(&p, g_u);  float* pu  = (float*)p;

    cudaFuncSetAttribute(gemm_xp1, cudaFuncAttributeMaxDynamicSharedMemorySize, GEMM_SMEM_BYTES);
    cudaFuncSetAttribute(gemm_u,   cudaFuncAttributeMaxDynamicSharedMemorySize, GEMM_SMEM_BYTES);
    cudaFuncSetAttribute(gemm_c1,  cudaFuncAttributeMaxDynamicSharedMemorySize, GEMM_SMEM_BYTES);

    init_streams_once();

    if (g_streams_ok) {
        zero_flags<<<1, 64>>>();

        cudaEventRecord(g_evFork, 0);
        cudaStreamWaitEvent(g_s1, g_evFork, 0);

        // side: XP for modules 6..0
        for (int m = 6; m >= 0; m--) {
            dim3 g(1, (unsigned)(1024 >> m));
            gemm_xp1<<<g, 256, GEMM_SMEM_BYTES, g_s1>>>(x, wih, m);
            cudaEventRecord(g_evXP[m], g_s1);
        }

        // main: XP7
        {
            dim3 g(1, 8);
            gemm_xp1<<<g, 256, GEMM_SMEM_BYTES>>>(x, wih, 7);
        }

        // cascade for j = 7..2 (C_j on side, gated on chain completion)
        for (int j = 7; j >= 2; j--) {
            CHAINS[j](whh, bih, bhh);
            cudaEventRecord(g_evChain[j], 0);

            cudaStreamWaitEvent(g_s1, g_evChain[j], 0);
            {
                dim3 gc(2, (unsigned)(1024 >> j));
                gemm_c1<<<gc, 256, GEMM_SMEM_BYTES, g_s1>>>(fcw, j);
            }

            dim3 g((unsigned)j, (unsigned)(1024 >> j));
            gemm_u<<<g, 256, GEMM_SMEM_BYTES>>>(
                pht + xpoff(j), whh + 128 * j, pu + uoff(j), 128 * j);
            cudaStreamWaitEvent(0, g_evXP[j - 1], 0);
        }
        cudaEventRecord(g_evU2, 0);   // U_2..U_7 + XP_1 done on main

        // main: chain 1 with inline U_1 producer
        chain1u<<<BATCH, 256>>>(whh, bih, bhh);
        cudaEventRecord(g_evChain[1], 0);

        // side: chain 0 consumer — gated ONLY on evU2 (+ XP_0 in-stream),
        // runs concurrently with chain1u.
        cudaStreamWaitEvent(g_s1, g_evU2, 0);
        chain0w<<<BATCH, 128, 0, g_s1>>>(whh, bih, bhh);

        // side: C_1 (after chain1u), C_0 (after chain0w, in-stream)
        cudaStreamWaitEvent(g_s1, g_evChain[1], 0);
        {
            dim3 gc(2, 512);
            gemm_c1<<<gc, 256, GEMM_SMEM_BYTES, g_s1>>>(fcw, 1);
        }
        {
            dim3 gc(2, 1024);
            gemm_c1<<<gc, 256, GEMM_SMEM_BYTES, g_s1>>>(fcw, 0);
        }
        cudaEventRecord(g_evSideEnd, g_s1);

        cudaStreamWaitEvent(0, g_evSideEnd, 0);
        gather_y<<<16384, 256>>>(fcb, out);
    } else {
        // ---- serial fallback ----
        zero_flags<<<1, 64>>>();
        for (int m = 7; m >= 0; m--) {
            dim3 g(1, (unsigned)(1024 >> m));
            gemm_xp1<<<g, 256, GEMM_SMEM_BYTES>>>(x, wih, m);
        }
        for (int j = 7; j >= 2; j--) {
            CHAINS[j](whh, bih, bhh);
            dim3 g((unsigned)j, (unsigned)(1024 >> j));
            gemm_u<<<g, 256, GEMM_SMEM_BYTES>>>(
                pht + xpoff(j), whh + 128 * j, pu + uoff(j), 128 * j);
        }
        chain1u<<<BATCH, 256>>>(whh, bih, bhh);
        chain0w<<<BATCH, 128>>>(whh, bih, bhh);
        for (int m = 7; m >= 0; m--) {
            dim3 g(2, (unsigned)(1024 >> m));
            gemm_c1<<<g, 256, GEMM_SMEM_BYTES>>>(fcw, m);
        }
        gather_y<<<16384, 256>>>(fcb, out);
    }
}